// round 3
// baseline (speedup 1.0000x reference)
#include <cuda_runtime.h>
#include <cuda_bf16.h>
#include <stdint.h>

#define ED 128
#define DHALF 64
#define TILE_M 128
#define THREADS 256
#define SB 136  // padded bf16 stride (272B rows -> conflict-free ldmatrix)

// ---------------- device globals ----------------
__device__ __nv_bfloat16 g_W1h[ED * ED];
__device__ __nv_bfloat16 g_W1l[ED * ED];
__device__ int g_idx64;

// ---------------- helpers ----------------
__device__ __forceinline__ uint32_t smem_u32(const void* p) {
    uint32_t a;
    asm("{ .reg .u64 t; cvta.to.shared.u64 t, %1; cvt.u32.u64 %0, t; }" : "=r"(a) : "l"(p));
    return a;
}
__device__ __forceinline__ void ldsm_x4(uint32_t* r, uint32_t addr) {
    asm volatile("ldmatrix.sync.aligned.m8n8.x4.shared.b16 {%0,%1,%2,%3}, [%4];"
                 : "=r"(r[0]), "=r"(r[1]), "=r"(r[2]), "=r"(r[3]) : "r"(addr));
}
__device__ __forceinline__ void mma16816(float* c, const uint32_t* a, uint32_t b0, uint32_t b1) {
    asm volatile("mma.sync.aligned.m16n8k16.row.col.f32.bf16.bf16.f32 "
                 "{%0,%1,%2,%3}, {%4,%5,%6,%7}, {%8,%9}, {%0,%1,%2,%3};"
                 : "+f"(c[0]), "+f"(c[1]), "+f"(c[2]), "+f"(c[3])
                 : "r"(a[0]), "r"(a[1]), "r"(a[2]), "r"(a[3]), "r"(b0), "r"(b1));
}

// smem layout (bytes)
#define SM_PART 0
#define SM_AH   1024
#define SM_AL   (SM_AH + TILE_M * SB * 2)
#define SM_BH   (SM_AL + TILE_M * SB * 2)
#define SM_BL   (SM_BH + ED * SB * 2)
#define SMEM_BYTES (SM_BL + ED * SB * 2)

// ---------------- prep: split W1 into bf16 hi/lo; sniff idx dtype ----------------
__global__ void pip_prep(const float* __restrict__ W1, const void* __restrict__ idxl,
                         long long P, long long Nnodes) {
    int i = blockIdx.x * blockDim.x + threadIdx.x;
    if (i < ED * ED) {
        float v = W1[i];
        __nv_bfloat16 h = __float2bfloat16(v);
        g_W1h[i] = h;
        g_W1l[i] = __float2bfloat16(v - __bfloat162float(h));
    }
    if (blockIdx.x == 0 && threadIdx.x == 0) {
        const unsigned long long* p64 = (const unsigned long long*)idxl;
        long long n = 512;
        if (2 * n > P) n = P / 2;
        int ok = 1;
        for (long long k = 0; k < n; k++)
            if (p64[k] >= (unsigned long long)Nnodes) { ok = 0; break; }
        g_idx64 = ok;
    }
}

// ---------------- main persistent kernel ----------------
extern "C" __global__ void __launch_bounds__(THREADS, 1)
pip_main(const float* __restrict__ g1, const float* __restrict__ g2,
         const void* __restrict__ idxl, const void* __restrict__ idxr,
         const float* __restrict__ b1, const float* __restrict__ W2,
         const float* __restrict__ b2, float* __restrict__ out,
         long long P, long long Nnodes) {
    extern __shared__ char smem[];
    uint32_t sb = smem_u32(smem);
    const int tid = threadIdx.x;
    const int wid = tid >> 5;
    const int lid = tid & 31;

    // ---- stage W1 hi/lo into padded smem [n][k] ----
    for (int i = tid; i < ED * DHALF; i += THREADS) {  // bf16x2 pairs
        int n = i >> 6, kp = i & 63;
        uint32_t off = (uint32_t)(n * SB + kp * 2) * 2;
        *(uint32_t*)(smem + SM_BH + off) = ((const uint32_t*)g_W1h)[i];
        *(uint32_t*)(smem + SM_BL + off) = ((const uint32_t*)g_W1l)[i];
    }
    __syncthreads();

    const int is64 = g_idx64;
    const float b2v = b2[0];

    // warp tiling: wm in [0,4), wn in [0,2); warp tile m32 x n64
    const int wm = wid >> 1;
    const int wn = wid & 1;
    const int m0 = wm * 32;

    // per-thread b1/w2 values for this warp's n-columns
    float b1v[16], w2v[16];
#pragma unroll
    for (int nt = 0; nt < 8; nt++) {
#pragma unroll
        for (int j = 0; j < 2; j++) {
            int n = wn * 64 + nt * 8 + (lid & 3) * 2 + j;
            b1v[nt * 2 + j] = b1[n];
            w2v[nt * 2 + j] = W2[n];
        }
    }

    // ldmatrix per-lane address components
    const int a_row = (lid & 7) + ((lid >> 3) & 1) * 8;
    const int a_kad = ((lid >> 4) & 1) * 8;
    const int b_row = (lid & 7) + ((lid >> 4) & 1) * 8;
    const int b_kad = ((lid >> 3) & 1) * 8;

    // gather assignment: warp covers rows [wid*16, wid*16+16)
    const float* gsrc = (lid < 16) ? g1 : g2;
    const void* isrc = (lid < 16) ? idxl : idxr;
    const int q = lid & 15;

    const long long nTiles = (P + TILE_M - 1) / TILE_M;
    float* s_part = (float*)(smem + SM_PART);  // [2][128]

    for (long long tile = blockIdx.x; tile < nTiles; tile += gridDim.x) {
        const long long base = tile * TILE_M;

        // ---- gather + split-convert into A_hi / A_lo ----
        long long idxv[16];
#pragma unroll
        for (int it = 0; it < 16; it++) {
            long long p = base + (long long)(wid * 16 + it);
            if (p >= P) p = 0;
            idxv[it] = is64 ? ((const long long*)isrc)[p]
                            : (long long)((const int*)isrc)[p];
        }
        float4 v[16];
#pragma unroll
        for (int it = 0; it < 16; it++)
            v[it] = ((const float4*)(gsrc + idxv[it] * DHALF))[q];
#pragma unroll
        for (int it = 0; it < 16; it++) {
            int r = wid * 16 + it;
            int c = ((lid < 16) ? 0 : 64) + q * 4;
            __nv_bfloat162 h0 = __float22bfloat162_rn(make_float2(v[it].x, v[it].y));
            __nv_bfloat162 h1 = __float22bfloat162_rn(make_float2(v[it].z, v[it].w));
            float2 f0 = __bfloat1622float2(h0);
            float2 f1 = __bfloat1622float2(h1);
            __nv_bfloat162 l0 = __float22bfloat162_rn(make_float2(v[it].x - f0.x, v[it].y - f0.y));
            __nv_bfloat162 l1 = __float22bfloat162_rn(make_float2(v[it].z - f1.x, v[it].w - f1.y));
            uint32_t off = (uint32_t)(r * SB + c) * 2;
            uint2 wh, wl;
            wh.x = *(uint32_t*)&h0; wh.y = *(uint32_t*)&h1;
            wl.x = *(uint32_t*)&l0; wl.y = *(uint32_t*)&l1;
            *(uint2*)(smem + SM_AH + off) = wh;
            *(uint2*)(smem + SM_AL + off) = wl;
        }
        __syncthreads();

        // ---- GEMM: c = Ah*Bh + Al*Bh + Ah*Bl ----
        float c[2][8][4];
#pragma unroll
        for (int mt = 0; mt < 2; mt++)
#pragma unroll
            for (int nt = 0; nt < 8; nt++)
#pragma unroll
                for (int j = 0; j < 4; j++) c[mt][nt][j] = 0.0f;

        for (int k0 = 0; k0 < 128; k0 += 16) {
            uint32_t ah[2][4], al[2][4];
#pragma unroll
            for (int mt = 0; mt < 2; mt++) {
                uint32_t ao = (uint32_t)((m0 + mt * 16 + a_row) * SB + k0 + a_kad) * 2;
                ldsm_x4(ah[mt], sb + SM_AH + ao);
                ldsm_x4(al[mt], sb + SM_AL + ao);
            }
#pragma unroll
            for (int nq = 0; nq < 4; nq++) {
                int n0 = wn * 64 + nq * 16;
                uint32_t bo = (uint32_t)((n0 + b_row) * SB + k0 + b_kad) * 2;
                uint32_t bh[4], bl[4];
                ldsm_x4(bh, sb + SM_BH + bo);
                ldsm_x4(bl, sb + SM_BL + bo);
#pragma unroll
                for (int mt = 0; mt < 2; mt++) {
#pragma unroll
                    for (int f = 0; f < 2; f++) {
                        float* cc = c[mt][nq * 2 + f];
                        mma16816(cc, ah[mt], bh[2 * f], bh[2 * f + 1]);
                        mma16816(cc, al[mt], bh[2 * f], bh[2 * f + 1]);
                        mma16816(cc, ah[mt], bl[2 * f], bl[2 * f + 1]);
                    }
                }
            }
        }

        // ---- epilogue: bias + relu + dot(W2), reduce over n ----
#pragma unroll
        for (int mt = 0; mt < 2; mt++) {
            float s0 = 0.0f, s1 = 0.0f;
#pragma unroll
            for (int nt = 0; nt < 8; nt++) {
#pragma unroll
                for (int j = 0; j < 2; j++) {
                    float bv = b1v[nt * 2 + j], wv = w2v[nt * 2 + j];
                    s0 = fmaf(fmaxf(c[mt][nt][j] + bv, 0.0f), wv, s0);
                    s1 = fmaf(fmaxf(c[mt][nt][2 + j] + bv, 0.0f), wv, s1);
                }
            }
            s0 += __shfl_xor_sync(0xFFFFFFFF, s0, 1);
            s0 += __shfl_xor_sync(0xFFFFFFFF, s0, 2);
            s1 += __shfl_xor_sync(0xFFFFFFFF, s1, 1);
            s1 += __shfl_xor_sync(0xFFFFFFFF, s1, 2);
            if ((lid & 3) == 0) {
                int row = m0 + mt * 16 + (lid >> 2);
                s_part[wn * 128 + row] = s0;
                s_part[wn * 128 + row + 8] = s1;
            }
        }
        __syncthreads();

        if (tid < TILE_M) {
            long long p = base + tid;
            if (p < P) out[p] = s_part[tid] + s_part[128 + tid] + b2v;
        }
        // A-tile reuse is safe: all warps passed the sync above after their MMA reads
    }
}

// ---------------- launch ----------------
extern "C" void kernel_launch(void* const* d_in, const int* in_sizes, int n_in,
                              void* d_out, int out_size) {
    const float* g1 = (const float*)d_in[0];
    const float* g2 = (const float*)d_in[1];
    const void* il = d_in[2];
    const void* ir = d_in[3];
    const float* W1 = (const float*)d_in[4];
    const float* b1 = (const float*)d_in[5];
    const float* W2 = (const float*)d_in[6];
    const float* b2 = (const float*)d_in[7];
    long long P = (long long)in_sizes[2];
    long long Nn = (long long)in_sizes[0] / DHALF;

    pip_prep<<<(ED * ED + 255) / 256, 256>>>(W1, il, P, Nn);

    cudaFuncSetAttribute(pip_main, cudaFuncAttributeMaxDynamicSharedMemorySize, SMEM_BYTES);
    int nsm = 148;
    cudaDeviceGetAttribute(&nsm, cudaDevAttrMultiProcessorCount, 0);
    long long nTiles = (P + TILE_M - 1) / TILE_M;
    int grid = (nTiles < (long long)nsm) ? (int)nTiles : nsm;

    pip_main<<<grid, THREADS, SMEM_BYTES>>>(g1, g2, il, ir, b1, W2, b2,
                                            (float*)d_out, P, Nn);
}